// round 14
// baseline (speedup 1.0000x reference)
#include <cuda_runtime.h>
#include <cuda_fp16.h>

#define BB 2048
#define NN 64
#define EPG 512
#define TOTAL_N (BB*NN)      // 131072
#define TOTAL_E (BB*EPG)     // 1048576
#define DN 16
#define DE 64
#define DU 32
#define DUE 64
#define HID 512
#define HID2 256
#define SDIM (NN*DE + DUE)   // 4160
#define KSPL 2080            // GEMM1 split-K half
#define KSPL3 128            // GEMM3 split-K half

// ---------------- scratch (no allocs allowed) ----------------
__device__ __half g_states[BB*SDIM];
__device__ float  g_h1p[2*BB*HID];
__device__ __half g_h1[BB*HID];
__device__ __half g_h2[BB*HID2];
__device__ float  g_lp[2*BB*NN];
__device__ __half g_w2h[SDIM*HID];
__device__ __half g_w3h[HID*HID2];
__device__ __half g_w4h[HID2*NN];

#define N2Q (SDIM*HID/4)
#define N3Q (HID*HID2/4)
#define N4Q (HID2*NN/4)

// ---------------- helpers ----------------
__device__ __forceinline__ unsigned s2u(const void* p) {
    return (unsigned)__cvta_generic_to_shared(p);
}

// ---------------- threefry2x32 (JAX, key = PRNGKey(42) = {0,42}) ----------------
__device__ __forceinline__ unsigned int rotl32(unsigned int v, int d) {
    return __funnelshift_l(v, v, d);
}

__device__ __forceinline__ unsigned int threefry_xor(unsigned int x0, unsigned int x1) {
    const unsigned int K0 = 0u, K1 = 42u;
    const unsigned int K2c = 0x1BD11BDAu ^ K0 ^ K1;
#define TF_ROUND(r) { x0 += x1; x1 = rotl32(x1, r); x1 ^= x0; }
    x0 += K0; x1 += K1;
    TF_ROUND(13) TF_ROUND(15) TF_ROUND(26) TF_ROUND(6)
    x0 += K1;  x1 += K2c + 1u;
    TF_ROUND(17) TF_ROUND(29) TF_ROUND(16) TF_ROUND(24)
    x0 += K2c; x1 += K0 + 2u;
    TF_ROUND(13) TF_ROUND(15) TF_ROUND(26) TF_ROUND(6)
    x0 += K0;  x1 += K1 + 3u;
    TF_ROUND(17) TF_ROUND(29) TF_ROUND(16) TF_ROUND(24)
    x0 += K1;  x1 += K2c + 4u;
    TF_ROUND(13) TF_ROUND(15) TF_ROUND(26) TF_ROUND(6)
    x0 += K2c; x1 += K0 + 5u;
#undef TF_ROUND
    return x0 ^ x1;
}

// ---------------- per-graph GNN kernel (+ fused weight fp16 conversion) --------
__global__ __launch_bounds__(256) void graph_kernel(
    const float* __restrict__ x, const float* __restrict__ edge_attr,
    const float* __restrict__ user_s,
    const float* __restrict__ W_msg, const float* __restrict__ b_msg,
    const float* __restrict__ W_edge, const float* __restrict__ b_edge,
    const float* __restrict__ W_self, const float* __restrict__ b_self,
    const float* __restrict__ W1, const float* __restrict__ b1,
    const int* __restrict__ edge_index,
    const float* __restrict__ W2f, const float* __restrict__ W3f,
    const float* __restrict__ W4f)
{
    __shared__ float sWm[DN][DE];
    __shared__ float sWs[DN][DE];
    __shared__ float sWe[2][DE];
    __shared__ float sbme[DE];
    __shared__ float sbs[DE];
    __shared__ __align__(16) float sx[NN][20];
    __shared__ __align__(16) float sxa[NN][20];
    __shared__ float2 sead[EPG];
    __shared__ float2 sea2[NN];
    __shared__ unsigned short slist[NN * 32];
    __shared__ int sdeg[NN];

    const int b = blockIdx.x;
    const int t = threadIdx.x;

    for (int i = t; i < DN * DE; i += 256) {
        sWm[i / DE][i % DE] = W_msg[i];
        sWs[i / DE][i % DE] = W_self[i];
    }
    for (int i = t; i < 2 * DE; i += 256) sWe[i / DE][i % DE] = W_edge[i];
    if (t < DE) { sbme[t] = b_msg[t] + b_edge[t]; sbs[t] = b_self[t]; }
    for (int i = t; i < NN * DN; i += 256) sx[i / DN][i % DN] = x[b * NN * DN + i];
    if (t < NN) sdeg[t] = 0;

    // fused weight conversion (fp32 -> fp16), spread across all blocks;
    // overlaps with this block's barrier/atomic latency.
    {
        const int total = N2Q + N3Q + N4Q;
        for (int i = b * 256 + t; i < total; i += BB * 256) {
            const float* s; __half* dp; int j;
            if (i < N2Q)            { s = W2f; dp = g_w2h; j = i; }
            else if (i < N2Q + N3Q) { s = W3f; dp = g_w3h; j = i - N2Q; }
            else                    { s = W4f; dp = g_w4h; j = i - N2Q - N3Q; }
            float4 v = ((const float4*)s)[j];
            ((__half2*)dp)[2 * j]     = __floats2half2_rn(v.x, v.y);
            ((__half2*)dp)[2 * j + 1] = __floats2half2_rn(v.z, v.w);
        }
    }
    __syncthreads();

    const int n = t >> 2;
    const int q = t & 3;

    // pass 1: one atomic per edge; slot index = returned count
    {
        const int ebase = b * EPG;
        for (int e = t; e < EPG; e += 256) {
            int src = edge_index[ebase + e] - b * NN;
            int dst = edge_index[TOTAL_E + ebase + e] - b * NN;
            int slot = atomicAdd(&sdeg[dst], 1);
            slist[(dst << 5) + slot] = (unsigned short)((e << 6) | src);
            sead[e] = ((const float2*)edge_attr)[ebase + e];
        }
    }
    __syncthreads();

    // gather: sum raw x over neighbors + edge attrs
    {
        float e0 = 0.f, e1 = 0.f;
        float4 xa = make_float4(0.f, 0.f, 0.f, 0.f);
        const int cnt = sdeg[n];
        const int lbase = n << 5;
        for (int i = 0; i < cnt; i++) {
            unsigned v = slist[lbase + i];
            int s = v & 63;
            float4 xv = *(const float4*)&sx[s][q * 4];
            xa.x += xv.x; xa.y += xv.y; xa.z += xv.z; xa.w += xv.w;
            float2 ea = sead[v >> 6];
            e0 += ea.x; e1 += ea.y;
        }
        *(float4*)&sxa[n][q * 4] = xa;
        if (q == 0) sea2[n] = make_float2(e0, e1);
    }
    __syncthreads();

    // epilogue, d-major: thread owns dim d for 16 nodes; weights in registers
    {
        const int d = t & 63, grp = t >> 6;
        float ws[DN], wm[DN];
        #pragma unroll
        for (int k = 0; k < DN; k++) { ws[k] = sWs[k][d]; wm[k] = sWm[k][d]; }
        const float we0 = sWe[0][d], we1 = sWe[1][d];
        const float bme = sbme[d],   bsv = sbs[d];

        unsigned mbits = 0;
        {
            unsigned base_idx = ((unsigned)(b * NN + grp * 16) << 6) + d;
            #pragma unroll 1
            for (int j = 0; j < 16; j++)
                mbits |= (((~threefry_xor(0u, base_idx + (j << 6))) >> 31) & 1u) << j;
        }

        #pragma unroll 4
        for (int j = 0; j < 16; j++) {
            const int n2 = grp * 16 + j;
            float4 x0 = *(const float4*)&sx[n2][0];
            float4 x1 = *(const float4*)&sx[n2][4];
            float4 x2 = *(const float4*)&sx[n2][8];
            float4 x3 = *(const float4*)&sx[n2][12];
            float4 a0 = *(const float4*)&sxa[n2][0];
            float4 a1 = *(const float4*)&sxa[n2][4];
            float4 a2 = *(const float4*)&sxa[n2][8];
            float4 a3 = *(const float4*)&sxa[n2][12];
            float acc = bsv;
            acc += x0.x*ws[0] + x0.y*ws[1] + x0.z*ws[2] + x0.w*ws[3];
            acc += x1.x*ws[4] + x1.y*ws[5] + x1.z*ws[6] + x1.w*ws[7];
            acc += x2.x*ws[8] + x2.y*ws[9] + x2.z*ws[10]+ x2.w*ws[11];
            acc += x3.x*ws[12]+ x3.y*ws[13]+ x3.z*ws[14]+ x3.w*ws[15];
            acc += a0.x*wm[0] + a0.y*wm[1] + a0.z*wm[2] + a0.w*wm[3];
            acc += a1.x*wm[4] + a1.y*wm[5] + a1.z*wm[6] + a1.w*wm[7];
            acc += a2.x*wm[8] + a2.y*wm[9] + a2.z*wm[10]+ a2.w*wm[11];
            acc += a3.x*wm[12]+ a3.y*wm[13]+ a3.z*wm[14]+ a3.w*wm[15];
            float2 ea = sea2[n2];
            float deg = (float)sdeg[n2];
            float u = acc + ea.x * we0 + ea.y * we1 + deg * bme;
            u = (u > 0.f) ? u * 2.f : 0.f;
            if (!((mbits >> j) & 1u)) u = 0.f;
            g_states[b * SDIM + n2 * DE + d] = __float2half_rn(u);
        }
    }

    // user embedding
    if (t < DUE) {
        float acc = b1[t];
        #pragma unroll
        for (int k = 0; k < DU; k++) acc += user_s[b * DU + k] * W1[k * DUE + t];
        g_states[b * SDIM + NN * DE + t] = __float2half_rn(fmaxf(acc, 0.f));
    }
}

// ---------------- fp16 tensor-core GEMM, cp.async 3-stage pipeline ----------------
__device__ __forceinline__ void mma_f16(float* d, const uint4& a, unsigned b0, unsigned b1) {
    asm volatile(
        "mma.sync.aligned.m16n8k16.row.col.f32.f16.f16.f32 "
        "{%0,%1,%2,%3}, {%4,%5,%6,%7}, {%8,%9}, {%0,%1,%2,%3};"
        : "+f"(d[0]), "+f"(d[1]), "+f"(d[2]), "+f"(d[3])
        : "r"(a.x), "r"(a.y), "r"(a.z), "r"(a.w), "r"(b0), "r"(b1));
}
__device__ __forceinline__ void ldsm4(uint4& r, unsigned addr) {
    asm volatile("ldmatrix.sync.aligned.m8n8.x4.shared.b16 {%0,%1,%2,%3}, [%4];"
                 : "=r"(r.x), "=r"(r.y), "=r"(r.z), "=r"(r.w) : "r"(addr));
}
__device__ __forceinline__ void ldsm4t(uint4& r, unsigned addr) {
    asm volatile("ldmatrix.sync.aligned.m8n8.x4.trans.shared.b16 {%0,%1,%2,%3}, [%4];"
                 : "=r"(r.x), "=r"(r.y), "=r"(r.z), "=r"(r.w) : "r"(addr));
}
#define CPA16(dst, src) asm volatile("cp.async.cg.shared.global [%0], [%1], 16;" :: "r"(dst), "l"(src))
#define CPA_COMMIT()    asm volatile("cp.async.commit_group;" ::: "memory")
#define CPA_WAIT1()     asm volatile("cp.async.wait_group 1;" ::: "memory")

// A stage: BMT rows x 32 halves (64B) padded to 80B/row  -> conflict-free ldsm
// B stage: 32 k-rows x BNT halves padded +16B/row         -> conflict-free ldsm.trans
template <int BMT, int BNT, bool PARTIAL, bool RELU, typename OutT>
__global__ __launch_bounds__(256) void hgemm(
    const __half* __restrict__ A, const __half* __restrict__ Bw,
    const float* __restrict__ bias, OutT* __restrict__ C,
    int M, int N, int K, int lda)
{
    constexpr int WN_CNT = (BNT == 128) ? 2 : 4;   // warps along n
    constexpr int NWID   = BNT / WN_CNT;           // 64 or 16
    constexpr int NT     = NWID / 8;               // 8 or 2
    constexpr int AG     = BMT / 64;
    constexpr int STG_A  = BMT * 80;
    constexpr int BPITCH = 2 * BNT + 16;           // 272 or 144
    constexpr int BSTG   = 32 * BPITCH;

    extern __shared__ char smem[];
    const unsigned sAu = s2u(smem);
    const unsigned sBu = sAu + 3 * STG_A;

    if (PARTIAL) {
        A  += (size_t)blockIdx.z * K;
        Bw += (size_t)blockIdx.z * K * N;
        C  += (size_t)blockIdx.z * M * N;
    }

    const int t = threadIdx.x, lane = t & 31, wid = t >> 5;
    const int wm = wid / WN_CNT, wn = wid % WN_CNT;
    const int m0 = blockIdx.y * BMT, n0 = blockIdx.x * BNT;

    const int ar = t >> 2, agc = t & 3;

    int aoff[2];
    #pragma unroll
    for (int mt = 0; mt < 2; mt++) {
        int row = wm * 32 + mt * 16 + (lane & 7) + (((lane >> 3) & 1) << 3);
        aoff[mt] = row * 80 + (((lane >> 4) & 1) << 4);
    }
    int boff[NT / 2];
    #pragma unroll
    for (int n2 = 0; n2 < NT / 2; n2++) {
        int krow = (lane & 7) + (((lane >> 3) & 1) << 3);
        int ncol = wn * NWID + n2 * 16 + (((lane >> 4) & 1) << 3);
        boff[n2] = krow * BPITCH + ncol * 2;
    }

    float acc[2][NT][4];
    #pragma unroll
    for (int i = 0; i < 2; i++)
        #pragma unroll
        for (int j = 0; j < NT; j++)
            #pragma unroll
            for (int k = 0; k < 4; k++) acc[i][j][k] = 0.f;

    const int nIter = K >> 5;

    #define ISSUE(st, k0)                                                         \
    {                                                                             \
        _Pragma("unroll")                                                         \
        for (int j = 0; j < AG; j++) {                                            \
            int r = ar + 64 * j;                                                  \
            unsigned d = sAu + (st) * STG_A + r * 80 + (agc << 4);                \
            CPA16(d, A + (size_t)(m0 + r) * lda + (k0) + (agc << 3));             \
        }                                                                         \
        if (BNT == 64) {                                                          \
            int r = t >> 3, bgg = t & 7;                                          \
            unsigned d = sBu + (st) * BSTG + r * BPITCH + (bgg << 4);             \
            CPA16(d, Bw + (size_t)((k0) + r) * N + n0 + (bgg << 3));              \
        } else {                                                                  \
            _Pragma("unroll")                                                     \
            for (int j = 0; j < 2; j++) {                                         \
                int r = (t >> 4) + j * 16, bgg = t & 15;                          \
                unsigned d = sBu + (st) * BSTG + r * BPITCH + (bgg << 4);         \
                CPA16(d, Bw + (size_t)((k0) + r) * N + n0 + (bgg << 3));          \
            }                                                                     \
        }                                                                         \
    }

    ISSUE(0, 0); CPA_COMMIT();
    ISSUE(1, 32); CPA_COMMIT();

    for (int it = 0; it < nIter; it++) {
        const int st = it % 3;
        CPA_WAIT1();
        __syncthreads();

        const unsigned aBase = sAu + st * STG_A;
        const unsigned bBase = sBu + st * BSTG;

        #pragma unroll
        for (int ks = 0; ks < 2; ks++) {
            uint4 af[2];
            #pragma unroll
            for (int mt = 0; mt < 2; mt++)
                ldsm4(af[mt], aBase + aoff[mt] + (ks << 5));
            uint4 bf[NT / 2];
            #pragma unroll
            for (int n2 = 0; n2 < NT / 2; n2++)
                ldsm4t(bf[n2], bBase + ks * 16 * BPITCH + boff[n2]);
            #pragma unroll
            for (int mt = 0; mt < 2; mt++)
                #pragma unroll
                for (int nt = 0; nt < NT; nt++) {
                    unsigned bb0 = (nt & 1) ? bf[nt >> 1].z : bf[nt >> 1].x;
                    unsigned bb1 = (nt & 1) ? bf[nt >> 1].w : bf[nt >> 1].y;
                    mma_f16(acc[mt][nt], af[mt], bb0, bb1);
                }
        }

        if (it + 2 < nIter) { const int ns = (it + 2) % 3; ISSUE(ns, (it + 2) << 5); }
        CPA_COMMIT();
    }
    #undef ISSUE

    #pragma unroll
    for (int mt = 0; mt < 2; mt++) {
        int r0 = m0 + wm * 32 + mt * 16 + (lane >> 2);
        #pragma unroll
        for (int nt = 0; nt < NT; nt++) {
            int c = n0 + wn * NWID + nt * 8 + ((lane & 3) << 1);
            float v0 = acc[mt][nt][0];
            float v1 = acc[mt][nt][1];
            float v2 = acc[mt][nt][2];
            float v3 = acc[mt][nt][3];
            if (PARTIAL) {
                *(float2*)&((float*)C)[(size_t)r0 * N + c]       = make_float2(v0, v1);
                *(float2*)&((float*)C)[(size_t)(r0 + 8) * N + c] = make_float2(v2, v3);
            } else {
                float bv0 = bias[c], bv1 = bias[c + 1];
                v0 += bv0; v1 += bv1; v2 += bv0; v3 += bv1;
                if (RELU) {
                    v0 = fmaxf(v0, 0.f); v1 = fmaxf(v1, 0.f);
                    v2 = fmaxf(v2, 0.f); v3 = fmaxf(v3, 0.f);
                }
                if (sizeof(OutT) == 2) {
                    *(__half2*)&((__half*)C)[(size_t)r0 * N + c]       = __floats2half2_rn(v0, v1);
                    *(__half2*)&((__half*)C)[(size_t)(r0 + 8) * N + c] = __floats2half2_rn(v2, v3);
                } else {
                    *(float2*)&((float*)C)[(size_t)r0 * N + c]       = make_float2(v0, v1);
                    *(float2*)&((float*)C)[(size_t)(r0 + 8) * N + c] = make_float2(v2, v3);
                }
            }
        }
    }
}

// ---------------- split-K reduce + bias + relu -> fp16 h1 (ILP=4) ----------------
__global__ __launch_bounds__(256) void reduce_relu(
    const float* __restrict__ p, const float* __restrict__ bias, __half* __restrict__ o)
{
    const int tid = blockIdx.x * 256 + threadIdx.x;   // grid 256 -> 65536 threads
    #pragma unroll
    for (int r = 0; r < 4; r++) {
        int i = tid + r * 65536;
        float4 a = ((const float4*)p)[i];
        float4 b = ((const float4*)p)[i + (BB * HID / 4)];
        int c = (i * 4) & (HID - 1);
        float4 bv = *(const float4*)&bias[c];
        __half2 r0 = __floats2half2_rn(fmaxf(a.x + b.x + bv.x, 0.f), fmaxf(a.y + b.y + bv.y, 0.f));
        __half2 r1 = __floats2half2_rn(fmaxf(a.z + b.z + bv.z, 0.f), fmaxf(a.w + b.w + bv.w, 0.f));
        ((__half2*)o)[2 * i]     = r0;
        ((__half2*)o)[2 * i + 1] = r1;
    }
}

// ---------------- softmax over BATCH axis, fused logits split-K reduce ----------
__global__ __launch_bounds__(512) void softmax_kernel(
    const float* __restrict__ lp, const float* __restrict__ b4, float* __restrict__ out)
{
    const int ncol = blockIdx.x;
    const int t = threadIdx.x;
    __shared__ float red[512];

    const float bv = b4[ncol];
    float lv[4];
    #pragma unroll
    for (int r = 0; r < 4; r++) {
        int idx = (t + r * 512) * NN + ncol;
        lv[r] = lp[idx] + lp[BB * NN + idx] + bv;
    }

    float mx = lv[0];
    #pragma unroll
    for (int r = 1; r < 4; r++) mx = fmaxf(mx, lv[r]);
    red[t] = mx; __syncthreads();
    for (int s = 256; s > 0; s >>= 1) { if (t < s) red[t] = fmaxf(red[t], red[t + s]); __syncthreads(); }
    mx = red[0]; __syncthreads();

    float sum = 0.f;
    #pragma unroll
    for (int r = 0; r < 4; r++) { lv[r] = __expf(lv[r] - mx); sum += lv[r]; }
    red[t] = sum; __syncthreads();
    for (int s = 256; s > 0; s >>= 1) { if (t < s) red[t] += red[t + s]; __syncthreads(); }
    float inv = 1.f / red[0];

    #pragma unroll
    for (int r = 0; r < 4; r++) out[(t + r * 512) * NN + ncol] = lv[r] * inv;
}

// ---------------- launch ----------------
extern "C" void kernel_launch(void* const* d_in, const int* in_sizes, int n_in,
                              void* d_out, int out_size)
{
    const float* x         = (const float*)d_in[0];
    const float* edge_attr = (const float*)d_in[1];
    const float* user_s    = (const float*)d_in[2];
    const float* W_msg     = (const float*)d_in[3];
    const float* b_msg     = (const float*)d_in[4];
    const float* W_edge    = (const float*)d_in[5];
    const float* b_edge    = (const float*)d_in[6];
    const float* W_self    = (const float*)d_in[7];
    const float* b_self    = (const float*)d_in[8];
    const float* W1        = (const float*)d_in[9];
    const float* b1        = (const float*)d_in[10];
    const float* W2        = (const float*)d_in[11];
    const float* b2        = (const float*)d_in[12];
    const float* W3        = (const float*)d_in[13];
    const float* b3        = (const float*)d_in[14];
    const float* W4        = (const float*)d_in[15];
    const float* b4        = (const float*)d_in[16];
    const int*   edge_index = (const int*)d_in[17];
    float* out = (float*)d_out;

    __half *states, *h1, *h2, *w2h, *w3h, *w4h;
    float *h1p, *lp;
    cudaGetSymbolAddress((void**)&states, g_states);
    cudaGetSymbolAddress((void**)&h1p, g_h1p);
    cudaGetSymbolAddress((void**)&h1, g_h1);
    cudaGetSymbolAddress((void**)&h2, g_h2);
    cudaGetSymbolAddress((void**)&lp, g_lp);
    cudaGetSymbolAddress((void**)&w2h, g_w2h);
    cudaGetSymbolAddress((void**)&w3h, g_w3h);
    cudaGetSymbolAddress((void**)&w4h, g_w4h);

    const int smemG1 = 3 * (128 * 80 + 32 * (2 * 128 + 16));   // 56832
    const int smem64 = 3 * (64 * 80 + 32 * (2 * 64 + 16));     // 29184

    cudaFuncSetAttribute((const void*)hgemm<128, 128, true, false, float>,
                         cudaFuncAttributeMaxDynamicSharedMemorySize, smemG1);
    cudaFuncSetAttribute((const void*)hgemm<64, 64, false, true, __half>,
                         cudaFuncAttributeMaxDynamicSharedMemorySize, smem64);
    cudaFuncSetAttribute((const void*)hgemm<64, 64, true, false, float>,
                         cudaFuncAttributeMaxDynamicSharedMemorySize, smem64);

    graph_kernel<<<BB, 256>>>(x, edge_attr, user_s, W_msg, b_msg, W_edge, b_edge,
                              W_self, b_self, W1, b1, edge_index, W2, W3, W4);

    // GEMM1: fp16, BM=128 x BN=128, split-K=2 -> fp32 partials
    hgemm<128, 128, true, false, float><<<dim3(HID / 128, BB / 128, 2), 256, smemG1>>>(
        states, w2h, b2, h1p, BB, HID, KSPL, SDIM);
    reduce_relu<<<256, 256>>>(h1p, b2, h1);

    hgemm<64, 64, false, true, __half><<<dim3(HID2 / 64, BB / 64), 256, smem64>>>(
        h1, w3h, b3, h2, BB, HID2, HID, HID);

    hgemm<64, 64, true, false, float><<<dim3(NN / 64, BB / 64, 2), 256, smem64>>>(
        h2, w4h, b4, lp, BB, NN, KSPL3, HID2);

    softmax_kernel<<<NN, 512>>>(lp, b4, out);
}

// round 16
// speedup vs baseline: 1.0143x; 1.0143x over previous
#include <cuda_runtime.h>
#include <cuda_fp16.h>

#define BB 2048
#define NN 64
#define EPG 512
#define TOTAL_N (BB*NN)      // 131072
#define TOTAL_E (BB*EPG)     // 1048576
#define DN 16
#define DE 64
#define DU 32
#define DUE 64
#define HID 512
#define HID2 256
#define SDIM (NN*DE + DUE)   // 4160

// ---------------- scratch (no allocs allowed) ----------------
__device__ __half g_states[BB*SDIM];
__device__ float  g_h1p[4*BB*HID];    // 4-way split-K partials (16 MB)
__device__ __half g_h1[BB*HID];
__device__ float  g_h2p[2*BB*HID2];   // GEMM2 split-K partials (4 MB)
__device__ __half g_h2[BB*HID2];
__device__ float  g_lp[2*BB*NN];
__device__ __half g_w2h[SDIM*HID];
__device__ __half g_w3h[HID*HID2];
__device__ __half g_w4h[HID2*NN];

#define N2Q (SDIM*HID/4)
#define N3Q (HID*HID2/4)
#define N4Q (HID2*NN/4)

// ---------------- helpers ----------------
__device__ __forceinline__ unsigned s2u(const void* p) {
    return (unsigned)__cvta_generic_to_shared(p);
}

// ---------------- threefry2x32 (JAX, key = PRNGKey(42) = {0,42}) ----------------
__device__ __forceinline__ unsigned int rotl32(unsigned int v, int d) {
    return __funnelshift_l(v, v, d);
}

__device__ __forceinline__ unsigned int threefry_xor(unsigned int x0, unsigned int x1) {
    const unsigned int K0 = 0u, K1 = 42u;
    const unsigned int K2c = 0x1BD11BDAu ^ K0 ^ K1;
#define TF_ROUND(r) { x0 += x1; x1 = rotl32(x1, r); x1 ^= x0; }
    x0 += K0; x1 += K1;
    TF_ROUND(13) TF_ROUND(15) TF_ROUND(26) TF_ROUND(6)
    x0 += K1;  x1 += K2c + 1u;
    TF_ROUND(17) TF_ROUND(29) TF_ROUND(16) TF_ROUND(24)
    x0 += K2c; x1 += K0 + 2u;
    TF_ROUND(13) TF_ROUND(15) TF_ROUND(26) TF_ROUND(6)
    x0 += K0;  x1 += K1 + 3u;
    TF_ROUND(17) TF_ROUND(29) TF_ROUND(16) TF_ROUND(24)
    x0 += K1;  x1 += K2c + 4u;
    TF_ROUND(13) TF_ROUND(15) TF_ROUND(26) TF_ROUND(6)
    x0 += K2c; x1 += K0 + 5u;
#undef TF_ROUND
    return x0 ^ x1;
}

// ---------------- per-graph GNN kernel (+ fused weight fp16 conversion) --------
__global__ __launch_bounds__(256) void graph_kernel(
    const float* __restrict__ x, const float* __restrict__ edge_attr,
    const float* __restrict__ user_s,
    const float* __restrict__ W_msg, const float* __restrict__ b_msg,
    const float* __restrict__ W_edge, const float* __restrict__ b_edge,
    const float* __restrict__ W_self, const float* __restrict__ b_self,
    const float* __restrict__ W1, const float* __restrict__ b1,
    const int* __restrict__ edge_index,
    const float* __restrict__ W2f, const float* __restrict__ W3f,
    const float* __restrict__ W4f)
{
    __shared__ float sWm[DN][DE];
    __shared__ float sWs[DN][DE];
    __shared__ float sWe[2][DE];
    __shared__ float sbme[DE];
    __shared__ float sbs[DE];
    __shared__ __align__(16) float sx[NN][20];
    __shared__ __align__(16) float sxa[NN][20];
    __shared__ float2 sead[EPG];
    __shared__ float2 sea2[NN];
    __shared__ unsigned short slist[NN * 32];
    __shared__ int sdeg[NN];

    const int b = blockIdx.x;
    const int t = threadIdx.x;

    for (int i = t; i < DN * DE; i += 256) {
        sWm[i / DE][i % DE] = W_msg[i];
        sWs[i / DE][i % DE] = W_self[i];
    }
    for (int i = t; i < 2 * DE; i += 256) sWe[i / DE][i % DE] = W_edge[i];
    if (t < DE) { sbme[t] = b_msg[t] + b_edge[t]; sbs[t] = b_self[t]; }
    for (int i = t; i < NN * DN; i += 256) sx[i / DN][i % DN] = x[b * NN * DN + i];
    if (t < NN) sdeg[t] = 0;

    // fused weight conversion (fp32 -> fp16), spread across all blocks
    {
        const int total = N2Q + N3Q + N4Q;
        for (int i = b * 256 + t; i < total; i += BB * 256) {
            const float* s; __half* dp; int j;
            if (i < N2Q)            { s = W2f; dp = g_w2h; j = i; }
            else if (i < N2Q + N3Q) { s = W3f; dp = g_w3h; j = i - N2Q; }
            else                    { s = W4f; dp = g_w4h; j = i - N2Q - N3Q; }
            float4 v = ((const float4*)s)[j];
            ((__half2*)dp)[2 * j]     = __floats2half2_rn(v.x, v.y);
            ((__half2*)dp)[2 * j + 1] = __floats2half2_rn(v.z, v.w);
        }
    }
    __syncthreads();

    const int n = t >> 2;
    const int q = t & 3;

    // pass 1: one atomic per edge; slot index = returned count
    {
        const int ebase = b * EPG;
        for (int e = t; e < EPG; e += 256) {
            int src = edge_index[ebase + e] - b * NN;
            int dst = edge_index[TOTAL_E + ebase + e] - b * NN;
            int slot = atomicAdd(&sdeg[dst], 1);
            slist[(dst << 5) + slot] = (unsigned short)((e << 6) | src);
            sead[e] = ((const float2*)edge_attr)[ebase + e];
        }
    }
    __syncthreads();

    // gather: sum raw x over neighbors + edge attrs
    {
        float e0 = 0.f, e1 = 0.f;
        float4 xa = make_float4(0.f, 0.f, 0.f, 0.f);
        const int cnt = sdeg[n];
        const int lbase = n << 5;
        for (int i = 0; i < cnt; i++) {
            unsigned v = slist[lbase + i];
            int s = v & 63;
            float4 xv = *(const float4*)&sx[s][q * 4];
            xa.x += xv.x; xa.y += xv.y; xa.z += xv.z; xa.w += xv.w;
            float2 ea = sead[v >> 6];
            e0 += ea.x; e1 += ea.y;
        }
        *(float4*)&sxa[n][q * 4] = xa;
        if (q == 0) sea2[n] = make_float2(e0, e1);
    }
    __syncthreads();

    // epilogue, d-major: thread owns dim d for 16 nodes; weights in registers
    {
        const int d = t & 63, grp = t >> 6;
        float ws[DN], wm[DN];
        #pragma unroll
        for (int k = 0; k < DN; k++) { ws[k] = sWs[k][d]; wm[k] = sWm[k][d]; }
        const float we0 = sWe[0][d], we1 = sWe[1][d];
        const float bme = sbme[d],   bsv = sbs[d];

        unsigned mbits = 0;
        {
            unsigned base_idx = ((unsigned)(b * NN + grp * 16) << 6) + d;
            #pragma unroll 1
            for (int j = 0; j < 16; j++)
                mbits |= (((~threefry_xor(0u, base_idx + (j << 6))) >> 31) & 1u) << j;
        }

        #pragma unroll 4
        for (int j = 0; j < 16; j++) {
            const int n2 = grp * 16 + j;
            float4 x0 = *(const float4*)&sx[n2][0];
            float4 x1 = *(const float4*)&sx[n2][4];
            float4 x2 = *(const float4*)&sx[n2][8];
            float4 x3 = *(const float4*)&sx[n2][12];
            float4 a0 = *(const float4*)&sxa[n2][0];
            float4 a1 = *(const float4*)&sxa[n2][4];
            float4 a2 = *(const float4*)&sxa[n2][8];
            float4 a3 = *(const float4*)&sxa[n2][12];
            float acc = bsv;
            acc += x0.x*ws[0] + x0.y*ws[1] + x0.z*ws[2] + x0.w*ws[3];
            acc += x1.x*ws[4] + x1.y*ws[5] + x1.z*ws[6] + x1.w*ws[7];
            acc += x2.x*ws[8] + x2.y*ws[9] + x2.z*ws[10]+ x2.w*ws[11];
            acc += x3.x*ws[12]+ x3.y*ws[13]+ x3.z*ws[14]+ x3.w*ws[15];
            acc += a0.x*wm[0] + a0.y*wm[1] + a0.z*wm[2] + a0.w*wm[3];
            acc += a1.x*wm[4] + a1.y*wm[5] + a1.z*wm[6] + a1.w*wm[7];
            acc += a2.x*wm[8] + a2.y*wm[9] + a2.z*wm[10]+ a2.w*wm[11];
            acc += a3.x*wm[12]+ a3.y*wm[13]+ a3.z*wm[14]+ a3.w*wm[15];
            float2 ea = sea2[n2];
            float deg = (float)sdeg[n2];
            float u = acc + ea.x * we0 + ea.y * we1 + deg * bme;
            u = (u > 0.f) ? u * 2.f : 0.f;
            if (!((mbits >> j) & 1u)) u = 0.f;
            g_states[b * SDIM + n2 * DE + d] = __float2half_rn(u);
        }
    }

    // user embedding
    if (t < DUE) {
        float acc = b1[t];
        #pragma unroll
        for (int k = 0; k < DU; k++) acc += user_s[b * DU + k] * W1[k * DUE + t];
        g_states[b * SDIM + NN * DE + t] = __float2half_rn(fmaxf(acc, 0.f));
    }
}

// ---------------- fp16 tensor-core GEMM, cp.async 3-stage pipeline ----------------
__device__ __forceinline__ void mma_f16(float* d, const uint4& a, unsigned b0, unsigned b1) {
    asm volatile(
        "mma.sync.aligned.m16n8k16.row.col.f32.f16.f16.f32 "
        "{%0,%1,%2,%3}, {%4,%5,%6,%7}, {%8,%9}, {%0,%1,%2,%3};"
        : "+f"(d[0]), "+f"(d[1]), "+f"(d[2]), "+f"(d[3])
        : "r"(a.x), "r"(a.y), "r"(a.z), "r"(a.w), "r"(b0), "r"(b1));
}
__device__ __forceinline__ void ldsm4(uint4& r, unsigned addr) {
    asm volatile("ldmatrix.sync.aligned.m8n8.x4.shared.b16 {%0,%1,%2,%3}, [%4];"
                 : "=r"(r.x), "=r"(r.y), "=r"(r.z), "=r"(r.w) : "r"(addr));
}
__device__ __forceinline__ void ldsm4t(uint4& r, unsigned addr) {
    asm volatile("ldmatrix.sync.aligned.m8n8.x4.trans.shared.b16 {%0,%1,%2,%3}, [%4];"
                 : "=r"(r.x), "=r"(r.y), "=r"(r.z), "=r"(r.w) : "r"(addr));
}
#define CPA16(dst, src) asm volatile("cp.async.cg.shared.global [%0], [%1], 16;" :: "r"(dst), "l"(src))
#define CPA_COMMIT()    asm volatile("cp.async.commit_group;" ::: "memory")
#define CPA_WAIT1()     asm volatile("cp.async.wait_group 1;" ::: "memory")

// A stage: BMT rows x 32 halves (64B) padded to 80B/row  -> conflict-free ldsm
// B stage: 32 k-rows x BNT halves padded +16B/row        -> conflict-free ldsm.trans
// PARTIAL: split-K; K = slab stride, Ktot = full K; last slab may be shorter.
template <int BMT, int BNT, bool PARTIAL, bool RELU, typename OutT>
__global__ __launch_bounds__(256) void hgemm(
    const __half* __restrict__ A, const __half* __restrict__ Bw,
    const float* __restrict__ bias, OutT* __restrict__ C,
    int M, int N, int K, int Ktot, int lda)
{
    constexpr int WN_CNT = (BNT == 128) ? 2 : 4;
    constexpr int NWID   = BNT / WN_CNT;
    constexpr int NT     = NWID / 8;
    constexpr int AG     = BMT / 64;
    constexpr int STG_A  = BMT * 80;
    constexpr int BPITCH = 2 * BNT + 16;
    constexpr int BSTG   = 32 * BPITCH;

    extern __shared__ char smem[];
    const unsigned sAu = s2u(smem);
    const unsigned sBu = sAu + 3 * STG_A;

    int klen = K;
    if (PARTIAL) {
        int k_off = blockIdx.z * K;
        klen = min(K, Ktot - k_off);
        A  += k_off;
        Bw += (size_t)k_off * N;
        C  += (size_t)blockIdx.z * M * N;
    }

    const int t = threadIdx.x, lane = t & 31, wid = t >> 5;
    const int wm = wid / WN_CNT, wn = wid % WN_CNT;
    const int m0 = blockIdx.y * BMT, n0 = blockIdx.x * BNT;

    const int ar = t >> 2, agc = t & 3;

    int aoff[2];
    #pragma unroll
    for (int mt = 0; mt < 2; mt++) {
        int row = wm * 32 + mt * 16 + (lane & 7) + (((lane >> 3) & 1) << 3);
        aoff[mt] = row * 80 + (((lane >> 4) & 1) << 4);
    }
    int boff[NT / 2];
    #pragma unroll
    for (int n2 = 0; n2 < NT / 2; n2++) {
        int krow = (lane & 7) + (((lane >> 3) & 1) << 3);
        int ncol = wn * NWID + n2 * 16 + (((lane >> 4) & 1) << 3);
        boff[n2] = krow * BPITCH + ncol * 2;
    }

    float acc[2][NT][4];
    #pragma unroll
    for (int i = 0; i < 2; i++)
        #pragma unroll
        for (int j = 0; j < NT; j++)
            #pragma unroll
            for (int k = 0; k < 4; k++) acc[i][j][k] = 0.f;

    const int nIter = klen >> 5;

    #define ISSUE(st, k0)                                                         \
    {                                                                             \
        _Pragma("unroll")                                                         \
        for (int j = 0; j < AG; j++) {                                            \
            int r = ar + 64 * j;                                                  \
            unsigned d = sAu + (st) * STG_A + r * 80 + (agc << 4);                \
            CPA16(d, A + (size_t)(m0 + r) * lda + (k0) + (agc << 3));             \
        }                                                                         \
        if (BNT == 64) {                                                          \
            int r = t >> 3, bgg = t & 7;                                          \
            unsigned d = sBu + (st) * BSTG + r * BPITCH + (bgg << 4);             \
            CPA16(d, Bw + (size_t)((k0) + r) * N + n0 + (bgg << 3));              \
        } else {                                                                  \
            _Pragma("unroll")                                                     \
            for (int j = 0; j < 2; j++) {                                         \
                int r = (t >> 4) + j * 16, bgg = t & 15;                          \
                unsigned d = sBu + (st) * BSTG + r * BPITCH + (bgg << 4);         \
                CPA16(d, Bw + (size_t)((k0) + r) * N + n0 + (bgg << 3));          \
            }                                                                     \
        }                                                                         \
    }

    ISSUE(0, 0); CPA_COMMIT();
    ISSUE(1, 32); CPA_COMMIT();

    for (int it = 0; it < nIter; it++) {
        const int st = it % 3;
        CPA_WAIT1();
        __syncthreads();

        const unsigned aBase = sAu + st * STG_A;
        const unsigned bBase = sBu + st * BSTG;

        #pragma unroll
        for (int ks = 0; ks < 2; ks++) {
            uint4 af[2];
            #pragma unroll
            for (int mt = 0; mt < 2; mt++)
                ldsm4(af[mt], aBase + aoff[mt] + (ks << 5));
            uint4 bf[NT / 2];
            #pragma unroll
            for (int n2 = 0; n2 < NT / 2; n2++)
                ldsm4t(bf[n2], bBase + ks * 16 * BPITCH + boff[n2]);
            #pragma unroll
            for (int mt = 0; mt < 2; mt++)
                #pragma unroll
                for (int nt = 0; nt < NT; nt++) {
                    unsigned bb0 = (nt & 1) ? bf[nt >> 1].z : bf[nt >> 1].x;
                    unsigned bb1 = (nt & 1) ? bf[nt >> 1].w : bf[nt >> 1].y;
                    mma_f16(acc[mt][nt], af[mt], bb0, bb1);
                }
        }

        if (it + 2 < nIter) { const int ns = (it + 2) % 3; ISSUE(ns, (it + 2) << 5); }
        CPA_COMMIT();
    }
    #undef ISSUE

    #pragma unroll
    for (int mt = 0; mt < 2; mt++) {
        int r0 = m0 + wm * 32 + mt * 16 + (lane >> 2);
        #pragma unroll
        for (int nt = 0; nt < NT; nt++) {
            int c = n0 + wn * NWID + nt * 8 + ((lane & 3) << 1);
            float v0 = acc[mt][nt][0];
            float v1 = acc[mt][nt][1];
            float v2 = acc[mt][nt][2];
            float v3 = acc[mt][nt][3];
            if (PARTIAL) {
                *(float2*)&((float*)C)[(size_t)r0 * N + c]       = make_float2(v0, v1);
                *(float2*)&((float*)C)[(size_t)(r0 + 8) * N + c] = make_float2(v2, v3);
            } else {
                float bv0 = bias[c], bv1 = bias[c + 1];
                v0 += bv0; v1 += bv1; v2 += bv0; v3 += bv1;
                if (RELU) {
                    v0 = fmaxf(v0, 0.f); v1 = fmaxf(v1, 0.f);
                    v2 = fmaxf(v2, 0.f); v3 = fmaxf(v3, 0.f);
                }
                if (sizeof(OutT) == 2) {
                    *(__half2*)&((__half*)C)[(size_t)r0 * N + c]       = __floats2half2_rn(v0, v1);
                    *(__half2*)&((__half*)C)[(size_t)(r0 + 8) * N + c] = __floats2half2_rn(v2, v3);
                } else {
                    *(float2*)&((float*)C)[(size_t)r0 * N + c]       = make_float2(v0, v1);
                    *(float2*)&((float*)C)[(size_t)(r0 + 8) * N + c] = make_float2(v2, v3);
                }
            }
        }
    }
}

// ---------------- GEMM1 4-way split-K reduce + bias + relu -> fp16 h1 ----------
__global__ __launch_bounds__(256) void reduce_relu(
    const float* __restrict__ p, const float* __restrict__ bias, __half* __restrict__ o)
{
    const int tid = blockIdx.x * 256 + threadIdx.x;   // grid 256 -> 65536 threads
    const int S = BB * HID / 4;
    #pragma unroll
    for (int r = 0; r < 4; r++) {
        int i = tid + r * 65536;
        float4 a = ((const float4*)p)[i];
        float4 b = ((const float4*)p)[i + S];
        float4 c4 = ((const float4*)p)[i + 2 * S];
        float4 d4 = ((const float4*)p)[i + 3 * S];
        int c = (i * 4) & (HID - 1);
        float4 bv = *(const float4*)&bias[c];
        __half2 r0 = __floats2half2_rn(
            fmaxf(a.x + b.x + c4.x + d4.x + bv.x, 0.f),
            fmaxf(a.y + b.y + c4.y + d4.y + bv.y, 0.f));
        __half2 r1 = __floats2half2_rn(
            fmaxf(a.z + b.z + c4.z + d4.z + bv.z, 0.f),
            fmaxf(a.w + b.w + c4.w + d4.w + bv.w, 0.f));
        ((__half2*)o)[2 * i]     = r0;
        ((__half2*)o)[2 * i + 1] = r1;
    }
}

// ---------------- GEMM2 2-way split-K reduce + bias + relu -> fp16 h2 ----------
__global__ __launch_bounds__(256) void reduce_relu2(
    const float* __restrict__ p, const float* __restrict__ bias, __half* __restrict__ o)
{
    const int tid = blockIdx.x * 256 + threadIdx.x;   // grid 128 -> 32768 threads
    const int S = BB * HID2 / 4;
    #pragma unroll
    for (int r = 0; r < 4; r++) {
        int i = tid + r * 32768;
        float4 a = ((const float4*)p)[i];
        float4 b = ((const float4*)p)[i + S];
        int c = (i * 4) & (HID2 - 1);
        float4 bv = *(const float4*)&bias[c];
        __half2 r0 = __floats2half2_rn(fmaxf(a.x + b.x + bv.x, 0.f), fmaxf(a.y + b.y + bv.y, 0.f));
        __half2 r1 = __floats2half2_rn(fmaxf(a.z + b.z + bv.z, 0.f), fmaxf(a.w + b.w + bv.w, 0.f));
        ((__half2*)o)[2 * i]     = r0;
        ((__half2*)o)[2 * i + 1] = r1;
    }
}

// ---------------- softmax over BATCH axis, fused logits split-K reduce ----------
__global__ __launch_bounds__(512) void softmax_kernel(
    const float* __restrict__ lp, const float* __restrict__ b4, float* __restrict__ out)
{
    const int ncol = blockIdx.x;
    const int t = threadIdx.x;
    __shared__ float red[512];

    const float bv = b4[ncol];
    float lv[4];
    #pragma unroll
    for (int r = 0; r < 4; r++) {
        int idx = (t + r * 512) * NN + ncol;
        lv[r] = lp[idx] + lp[BB * NN + idx] + bv;
    }

    float mx = lv[0];
    #pragma unroll
    for (int r = 1; r < 4; r++) mx = fmaxf(mx, lv[r]);
    red[t] = mx; __syncthreads();
    for (int s = 256; s > 0; s >>= 1) { if (t < s) red[t] = fmaxf(red[t], red[t + s]); __syncthreads(); }
    mx = red[0]; __syncthreads();

    float sum = 0.f;
    #pragma unroll
    for (int r = 0; r < 4; r++) { lv[r] = __expf(lv[r] - mx); sum += lv[r]; }
    red[t] = sum; __syncthreads();
    for (int s = 256; s > 0; s >>= 1) { if (t < s) red[t] += red[t + s]; __syncthreads(); }
    float inv = 1.f / red[0];

    #pragma unroll
    for (int r = 0; r < 4; r++) out[(t + r * 512) * NN + ncol] = lv[r] * inv;
}

// ---------------- launch ----------------
extern "C" void kernel_launch(void* const* d_in, const int* in_sizes, int n_in,
                              void* d_out, int out_size)
{
    const float* x         = (const float*)d_in[0];
    const float* edge_attr = (const float*)d_in[1];
    const float* user_s    = (const float*)d_in[2];
    const float* W_msg     = (const float*)d_in[3];
    const float* b_msg     = (const float*)d_in[4];
    const float* W_edge    = (const float*)d_in[5];
    const float* b_edge    = (const float*)d_in[6];
    const float* W_self    = (const float*)d_in[7];
    const float* b_self    = (const float*)d_in[8];
    const float* W1        = (const float*)d_in[9];
    const float* b1        = (const float*)d_in[10];
    const float* W2        = (const float*)d_in[11];
    const float* b2        = (const float*)d_in[12];
    const float* W3        = (const float*)d_in[13];
    const float* b3        = (const float*)d_in[14];
    const float* W4        = (const float*)d_in[15];
    const float* b4        = (const float*)d_in[16];
    const int*   edge_index = (const int*)d_in[17];
    float* out = (float*)d_out;

    __half *states, *h1, *h2, *w2h, *w3h, *w4h;
    float *h1p, *h2p, *lp;
    cudaGetSymbolAddress((void**)&states, g_states);
    cudaGetSymbolAddress((void**)&h1p, g_h1p);
    cudaGetSymbolAddress((void**)&h1, g_h1);
    cudaGetSymbolAddress((void**)&h2p, g_h2p);
    cudaGetSymbolAddress((void**)&h2, g_h2);
    cudaGetSymbolAddress((void**)&lp, g_lp);
    cudaGetSymbolAddress((void**)&w2h, g_w2h);
    cudaGetSymbolAddress((void**)&w3h, g_w3h);
    cudaGetSymbolAddress((void**)&w4h, g_w4h);

    const int smemG1 = 3 * (128 * 80 + 32 * (2 * 128 + 16));   // 56832
    const int smem64 = 3 * (64 * 80 + 32 * (2 * 64 + 16));     // 29184

    cudaFuncSetAttribute((const void*)hgemm<128, 128, true, false, float>,
                         cudaFuncAttributeMaxDynamicSharedMemorySize, smemG1);
    cudaFuncSetAttribute((const void*)hgemm<64, 64, true, false, float>,
                         cudaFuncAttributeMaxDynamicSharedMemorySize, smem64);

    graph_kernel<<<BB, 256>>>(x, edge_attr, user_s, W_msg, b_msg, W_edge, b_edge,
                              W_self, b_self, W1, b1, edge_index, W2, W3, W4);

    // GEMM1: fp16, BM=128 x BN=128, split-K=4 (1056/1056/1056/992) -> fp32 partials
    hgemm<128, 128, true, false, float><<<dim3(HID / 128, BB / 128, 4), 256, smemG1>>>(
        states, w2h, b2, h1p, BB, HID, 1056, SDIM, SDIM);
    reduce_relu<<<256, 256>>>(h1p, b2, h1);

    // GEMM2: split-K=2 (256 each) -> fp32 partials -> reduce+bias+relu
    hgemm<64, 64, true, false, float><<<dim3(HID2 / 64, BB / 64, 2), 256, smem64>>>(
        h1, w3h, b3, h2p, BB, HID2, 256, HID, HID);
    reduce_relu2<<<128, 256>>>(h2p, b3, h2);

    // GEMM3: split-K=2 (128 each)
    hgemm<64, 64, true, false, float><<<dim3(NN / 64, BB / 64, 2), 256, smem64>>>(
        h2, w4h, b4, lp, BB, NN, 128, HID2, HID2);

    softmax_kernel<<<NN, 512>>>(lp, b4, out);
}

// round 17
// speedup vs baseline: 1.0463x; 1.0315x over previous
#include <cuda_runtime.h>
#include <cuda_fp16.h>

#define BB 2048
#define NN 64
#define EPG 512
#define TOTAL_N (BB*NN)      // 131072
#define TOTAL_E (BB*EPG)     // 1048576
#define DN 16
#define DE 64
#define DU 32
#define DUE 64
#define HID 512
#define HID2 256
#define SDIM (NN*DE + DUE)   // 4160

// ---------------- scratch (no allocs allowed) ----------------
__device__ __half g_states[BB*SDIM];
__device__ float  g_h1p[4*BB*HID];    // GEMM1 4-way split-K partials (16 MB)
__device__ __half g_h1[BB*HID];
__device__ float  g_h2p[2*BB*HID2];   // GEMM2 split-K partials (4 MB)
__device__ __half g_h2[BB*HID2];
__device__ float  g_lp[4*BB*NN];      // GEMM3 4-way split-K partials
__device__ __half g_w2h[SDIM*HID];
__device__ __half g_w3h[HID*HID2];
__device__ __half g_w4h[HID2*NN];

#define N2Q (SDIM*HID/4)
#define N3Q (HID*HID2/4)
#define N4Q (HID2*NN/4)

// ---------------- helpers ----------------
__device__ __forceinline__ unsigned s2u(const void* p) {
    return (unsigned)__cvta_generic_to_shared(p);
}

// ---------------- threefry2x32 (JAX, key = PRNGKey(42) = {0,42}) ----------------
__device__ __forceinline__ unsigned int rotl32(unsigned int v, int d) {
    return __funnelshift_l(v, v, d);
}

__device__ __forceinline__ unsigned int threefry_xor(unsigned int x0, unsigned int x1) {
    const unsigned int K0 = 0u, K1 = 42u;
    const unsigned int K2c = 0x1BD11BDAu ^ K0 ^ K1;
#define TF_ROUND(r) { x0 += x1; x1 = rotl32(x1, r); x1 ^= x0; }
    x0 += K0; x1 += K1;
    TF_ROUND(13) TF_ROUND(15) TF_ROUND(26) TF_ROUND(6)
    x0 += K1;  x1 += K2c + 1u;
    TF_ROUND(17) TF_ROUND(29) TF_ROUND(16) TF_ROUND(24)
    x0 += K2c; x1 += K0 + 2u;
    TF_ROUND(13) TF_ROUND(15) TF_ROUND(26) TF_ROUND(6)
    x0 += K0;  x1 += K1 + 3u;
    TF_ROUND(17) TF_ROUND(29) TF_ROUND(16) TF_ROUND(24)
    x0 += K1;  x1 += K2c + 4u;
    TF_ROUND(13) TF_ROUND(15) TF_ROUND(26) TF_ROUND(6)
    x0 += K2c; x1 += K0 + 5u;
#undef TF_ROUND
    return x0 ^ x1;
}

// ---------------- per-graph GNN kernel (+ fused weight fp16 conversion) --------
// 5 CTAs/SM target: regs <= 51, occ ~62%. Threefry hoisted to the top so its
// ALU work issues under the load/atomic-phase memory latency.
__global__ __launch_bounds__(256, 5) void graph_kernel(
    const float* __restrict__ x, const float* __restrict__ edge_attr,
    const float* __restrict__ user_s,
    const float* __restrict__ W_msg, const float* __restrict__ b_msg,
    const float* __restrict__ W_edge, const float* __restrict__ b_edge,
    const float* __restrict__ W_self, const float* __restrict__ b_self,
    const float* __restrict__ W1, const float* __restrict__ b1,
    const int* __restrict__ edge_index,
    const float* __restrict__ W2f, const float* __restrict__ W3f,
    const float* __restrict__ W4f)
{
    __shared__ float sWm[DN][DE];
    __shared__ float sWs[DN][DE];
    __shared__ float sWe[2][DE];
    __shared__ float sbme[DE];
    __shared__ float sbs[DE];
    __shared__ __align__(16) float sx[NN][20];
    __shared__ __align__(16) float sxa[NN][20];
    __shared__ float2 sead[EPG];
    __shared__ float2 sea2[NN];
    __shared__ unsigned short slist[NN * 32];
    __shared__ int sdeg[NN];

    const int b = blockIdx.x;
    const int t = threadIdx.x;

    // ---- dropout mask bits FIRST (pure ALU, no dependencies) ----
    // d-major mapping used by the epilogue: element idx = (b*NN + grp*16 + j)*64 + d
    unsigned mbits = 0;
    {
        const int d = t & 63, grp = t >> 6;
        unsigned base_idx = ((unsigned)(b * NN + grp * 16) << 6) + d;
        #pragma unroll 2
        for (int j = 0; j < 16; j++)
            mbits |= (((~threefry_xor(0u, base_idx + (j << 6))) >> 31) & 1u) << j;
    }

    for (int i = t; i < DN * DE; i += 256) {
        sWm[i / DE][i % DE] = W_msg[i];
        sWs[i / DE][i % DE] = W_self[i];
    }
    for (int i = t; i < 2 * DE; i += 256) sWe[i / DE][i % DE] = W_edge[i];
    if (t < DE) { sbme[t] = b_msg[t] + b_edge[t]; sbs[t] = b_self[t]; }
    for (int i = t; i < NN * DN; i += 256) sx[i / DN][i % DN] = x[b * NN * DN + i];
    if (t < NN) sdeg[t] = 0;

    // fused weight conversion (fp32 -> fp16), spread across all blocks
    {
        const int total = N2Q + N3Q + N4Q;
        for (int i = b * 256 + t; i < total; i += BB * 256) {
            const float* s; __half* dp; int j;
            if (i < N2Q)            { s = W2f; dp = g_w2h; j = i; }
            else if (i < N2Q + N3Q) { s = W3f; dp = g_w3h; j = i - N2Q; }
            else                    { s = W4f; dp = g_w4h; j = i - N2Q - N3Q; }
            float4 v = ((const float4*)s)[j];
            ((__half2*)dp)[2 * j]     = __floats2half2_rn(v.x, v.y);
            ((__half2*)dp)[2 * j + 1] = __floats2half2_rn(v.z, v.w);
        }
    }
    __syncthreads();

    const int n = t >> 2;
    const int q = t & 3;

    // pass 1: one atomic per edge; slot index = returned count
    {
        const int ebase = b * EPG;
        for (int e = t; e < EPG; e += 256) {
            int src = edge_index[ebase + e] - b * NN;
            int dst = edge_index[TOTAL_E + ebase + e] - b * NN;
            int slot = atomicAdd(&sdeg[dst], 1);
            slist[(dst << 5) + slot] = (unsigned short)((e << 6) | src);
            sead[e] = ((const float2*)edge_attr)[ebase + e];
        }
    }
    __syncthreads();

    // gather: sum raw x over neighbors + edge attrs
    {
        float e0 = 0.f, e1 = 0.f;
        float4 xa = make_float4(0.f, 0.f, 0.f, 0.f);
        const int cnt = sdeg[n];
        const int lbase = n << 5;
        for (int i = 0; i < cnt; i++) {
            unsigned v = slist[lbase + i];
            int s = v & 63;
            float4 xv = *(const float4*)&sx[s][q * 4];
            xa.x += xv.x; xa.y += xv.y; xa.z += xv.z; xa.w += xv.w;
            float2 ea = sead[v >> 6];
            e0 += ea.x; e1 += ea.y;
        }
        *(float4*)&sxa[n][q * 4] = xa;
        if (q == 0) sea2[n] = make_float2(e0, e1);
    }
    __syncthreads();

    // epilogue, d-major: thread owns dim d for 16 nodes; weights in registers
    {
        const int d = t & 63, grp = t >> 6;
        float ws[DN], wm[DN];
        #pragma unroll
        for (int k = 0; k < DN; k++) { ws[k] = sWs[k][d]; wm[k] = sWm[k][d]; }
        const float we0 = sWe[0][d], we1 = sWe[1][d];
        const float bme = sbme[d],   bsv = sbs[d];

        #pragma unroll 4
        for (int j = 0; j < 16; j++) {
            const int n2 = grp * 16 + j;
            float4 x0 = *(const float4*)&sx[n2][0];
            float4 x1 = *(const float4*)&sx[n2][4];
            float4 x2 = *(const float4*)&sx[n2][8];
            float4 x3 = *(const float4*)&sx[n2][12];
            float4 a0 = *(const float4*)&sxa[n2][0];
            float4 a1 = *(const float4*)&sxa[n2][4];
            float4 a2 = *(const float4*)&sxa[n2][8];
            float4 a3 = *(const float4*)&sxa[n2][12];
            float acc = bsv;
            acc += x0.x*ws[0] + x0.y*ws[1] + x0.z*ws[2] + x0.w*ws[3];
            acc += x1.x*ws[4] + x1.y*ws[5] + x1.z*ws[6] + x1.w*ws[7];
            acc += x2.x*ws[8] + x2.y*ws[9] + x2.z*ws[10]+ x2.w*ws[11];
            acc += x3.x*ws[12]+ x3.y*ws[13]+ x3.z*ws[14]+ x3.w*ws[15];
            acc += a0.x*wm[0] + a0.y*wm[1] + a0.z*wm[2] + a0.w*wm[3];
            acc += a1.x*wm[4] + a1.y*wm[5] + a1.z*wm[6] + a1.w*wm[7];
            acc += a2.x*wm[8] + a2.y*wm[9] + a2.z*wm[10]+ a2.w*wm[11];
            acc += a3.x*wm[12]+ a3.y*wm[13]+ a3.z*wm[14]+ a3.w*wm[15];
            float2 ea = sea2[n2];
            float deg = (float)sdeg[n2];
            float u = acc + ea.x * we0 + ea.y * we1 + deg * bme;
            u = (u > 0.f) ? u * 2.f : 0.f;
            if (!((mbits >> j) & 1u)) u = 0.f;
            g_states[b * SDIM + n2 * DE + d] = __float2half_rn(u);
        }
    }

    // user embedding
    if (t < DUE) {
        float acc = b1[t];
        #pragma unroll
        for (int k = 0; k < DU; k++) acc += user_s[b * DU + k] * W1[k * DUE + t];
        g_states[b * SDIM + NN * DE + t] = __float2half_rn(fmaxf(acc, 0.f));
    }
}

// ---------------- fp16 tensor-core GEMM, cp.async 3-stage pipeline ----------------
__device__ __forceinline__ void mma_f16(float* d, const uint4& a, unsigned b0, unsigned b1) {
    asm volatile(
        "mma.sync.aligned.m16n8k16.row.col.f32.f16.f16.f32 "
        "{%0,%1,%2,%3}, {%4,%5,%6,%7}, {%8,%9}, {%0,%1,%2,%3};"
        : "+f"(d[0]), "+f"(d[1]), "+f"(d[2]), "+f"(d[3])
        : "r"(a.x), "r"(a.y), "r"(a.z), "r"(a.w), "r"(b0), "r"(b1));
}
__device__ __forceinline__ void ldsm4(uint4& r, unsigned addr) {
    asm volatile("ldmatrix.sync.aligned.m8n8.x4.shared.b16 {%0,%1,%2,%3}, [%4];"
                 : "=r"(r.x), "=r"(r.y), "=r"(r.z), "=r"(r.w) : "r"(addr));
}
__device__ __forceinline__ void ldsm4t(uint4& r, unsigned addr) {
    asm volatile("ldmatrix.sync.aligned.m8n8.x4.trans.shared.b16 {%0,%1,%2,%3}, [%4];"
                 : "=r"(r.x), "=r"(r.y), "=r"(r.z), "=r"(r.w) : "r"(addr));
}
#define CPA16(dst, src) asm volatile("cp.async.cg.shared.global [%0], [%1], 16;" :: "r"(dst), "l"(src))
#define CPA_COMMIT()    asm volatile("cp.async.commit_group;" ::: "memory")
#define CPA_WAIT1()     asm volatile("cp.async.wait_group 1;" ::: "memory")

// A stage: BMT rows x 32 halves (64B) padded to 80B/row  -> conflict-free ldsm
// B stage: 32 k-rows x BNT halves padded +16B/row        -> conflict-free ldsm.trans
// PARTIAL: split-K; K = slab stride, Ktot = full K; last slab may be shorter.
template <int BMT, int BNT, bool PARTIAL, bool RELU, typename OutT>
__global__ __launch_bounds__(256) void hgemm(
    const __half* __restrict__ A, const __half* __restrict__ Bw,
    const float* __restrict__ bias, OutT* __restrict__ C,
    int M, int N, int K, int Ktot, int lda)
{
    constexpr int WN_CNT = (BNT == 128) ? 2 : 4;
    constexpr int NWID   = BNT / WN_CNT;
    constexpr int NT     = NWID / 8;
    constexpr int AG     = BMT / 64;
    constexpr int STG_A  = BMT * 80;
    constexpr int BPITCH = 2 * BNT + 16;
    constexpr int BSTG   = 32 * BPITCH;

    extern __shared__ char smem[];
    const unsigned sAu = s2u(smem);
    const unsigned sBu = sAu + 3 * STG_A;

    int klen = K;
    if (PARTIAL) {
        int k_off = blockIdx.z * K;
        klen = min(K, Ktot - k_off);
        A  += k_off;
        Bw += (size_t)k_off * N;
        C  += (size_t)blockIdx.z * M * N;
    }

    const int t = threadIdx.x, lane = t & 31, wid = t >> 5;
    const int wm = wid / WN_CNT, wn = wid % WN_CNT;
    const int m0 = blockIdx.y * BMT, n0 = blockIdx.x * BNT;

    const int ar = t >> 2, agc = t & 3;

    int aoff[2];
    #pragma unroll
    for (int mt = 0; mt < 2; mt++) {
        int row = wm * 32 + mt * 16 + (lane & 7) + (((lane >> 3) & 1) << 3);
        aoff[mt] = row * 80 + (((lane >> 4) & 1) << 4);
    }
    int boff[NT / 2];
    #pragma unroll
    for (int n2 = 0; n2 < NT / 2; n2++) {
        int krow = (lane & 7) + (((lane >> 3) & 1) << 3);
        int ncol = wn * NWID + n2 * 16 + (((lane >> 4) & 1) << 3);
        boff[n2] = krow * BPITCH + ncol * 2;
    }

    float acc[2][NT][4];
    #pragma unroll
    for (int i = 0; i < 2; i++)
        #pragma unroll
        for (int j = 0; j < NT; j++)
            #pragma unroll
            for (int k = 0; k < 4; k++) acc[i][j][k] = 0.f;

    const int nIter = klen >> 5;

    #define ISSUE(st, k0)                                                         \
    {                                                                             \
        _Pragma("unroll")                                                         \
        for (int j = 0; j < AG; j++) {                                            \
            int r = ar + 64 * j;                                                  \
            unsigned d = sAu + (st) * STG_A + r * 80 + (agc << 4);                \
            CPA16(d, A + (size_t)(m0 + r) * lda + (k0) + (agc << 3));             \
        }                                                                         \
        if (BNT == 64) {                                                          \
            int r = t >> 3, bgg = t & 7;                                          \
            unsigned d = sBu + (st) * BSTG + r * BPITCH + (bgg << 4);             \
            CPA16(d, Bw + (size_t)((k0) + r) * N + n0 + (bgg << 3));              \
        } else {                                                                  \
            _Pragma("unroll")                                                     \
            for (int j = 0; j < 2; j++) {                                         \
                int r = (t >> 4) + j * 16, bgg = t & 15;                          \
                unsigned d = sBu + (st) * BSTG + r * BPITCH + (bgg << 4);         \
                CPA16(d, Bw + (size_t)((k0) + r) * N + n0 + (bgg << 3));          \
            }                                                                     \
        }                                                                         \
    }

    ISSUE(0, 0); CPA_COMMIT();
    ISSUE(1, 32); CPA_COMMIT();

    for (int it = 0; it < nIter; it++) {
        const int st = it % 3;
        CPA_WAIT1();
        __syncthreads();

        const unsigned aBase = sAu + st * STG_A;
        const unsigned bBase = sBu + st * BSTG;

        #pragma unroll
        for (int ks = 0; ks < 2; ks++) {
            uint4 af[2];
            #pragma unroll
            for (int mt = 0; mt < 2; mt++)
                ldsm4(af[mt], aBase + aoff[mt] + (ks << 5));
            uint4 bf[NT / 2];
            #pragma unroll
            for (int n2 = 0; n2 < NT / 2; n2++)
                ldsm4t(bf[n2], bBase + ks * 16 * BPITCH + boff[n2]);
            #pragma unroll
            for (int mt = 0; mt < 2; mt++)
                #pragma unroll
                for (int nt = 0; nt < NT; nt++) {
                    unsigned bb0 = (nt & 1) ? bf[nt >> 1].z : bf[nt >> 1].x;
                    unsigned bb1 = (nt & 1) ? bf[nt >> 1].w : bf[nt >> 1].y;
                    mma_f16(acc[mt][nt], af[mt], bb0, bb1);
                }
        }

        if (it + 2 < nIter) { const int ns = (it + 2) % 3; ISSUE(ns, (it + 2) << 5); }
        CPA_COMMIT();
    }
    #undef ISSUE

    #pragma unroll
    for (int mt = 0; mt < 2; mt++) {
        int r0 = m0 + wm * 32 + mt * 16 + (lane >> 2);
        #pragma unroll
        for (int nt = 0; nt < NT; nt++) {
            int c = n0 + wn * NWID + nt * 8 + ((lane & 3) << 1);
            float v0 = acc[mt][nt][0];
            float v1 = acc[mt][nt][1];
            float v2 = acc[mt][nt][2];
            float v3 = acc[mt][nt][3];
            if (PARTIAL) {
                *(float2*)&((float*)C)[(size_t)r0 * N + c]       = make_float2(v0, v1);
                *(float2*)&((float*)C)[(size_t)(r0 + 8) * N + c] = make_float2(v2, v3);
            } else {
                float bv0 = bias[c], bv1 = bias[c + 1];
                v0 += bv0; v1 += bv1; v2 += bv0; v3 += bv1;
                if (RELU) {
                    v0 = fmaxf(v0, 0.f); v1 = fmaxf(v1, 0.f);
                    v2 = fmaxf(v2, 0.f); v3 = fmaxf(v3, 0.f);
                }
                if (sizeof(OutT) == 2) {
                    *(__half2*)&((__half*)C)[(size_t)r0 * N + c]       = __floats2half2_rn(v0, v1);
                    *(__half2*)&((__half*)C)[(size_t)(r0 + 8) * N + c] = __floats2half2_rn(v2, v3);
                } else {
                    *(float2*)&((float*)C)[(size_t)r0 * N + c]       = make_float2(v0, v1);
                    *(float2*)&((float*)C)[(size_t)(r0 + 8) * N + c] = make_float2(v2, v3);
                }
            }
        }
    }
}

// ---------------- GEMM1 4-way split-K reduce + bias + relu -> fp16 h1 ----------
__global__ __launch_bounds__(256) void reduce_relu(
    const float* __restrict__ p, const float* __restrict__ bias, __half* __restrict__ o)
{
    const int tid = blockIdx.x * 256 + threadIdx.x;   // grid 256 -> 65536 threads
    const int S = BB * HID / 4;
    #pragma unroll
    for (int r = 0; r < 4; r++) {
        int i = tid + r * 65536;
        float4 a = ((const float4*)p)[i];
        float4 b = ((const float4*)p)[i + S];
        float4 c4 = ((const float4*)p)[i + 2 * S];
        float4 d4 = ((const float4*)p)[i + 3 * S];
        int c = (i * 4) & (HID - 1);
        float4 bv = *(const float4*)&bias[c];
        __half2 r0 = __floats2half2_rn(
            fmaxf(a.x + b.x + c4.x + d4.x + bv.x, 0.f),
            fmaxf(a.y + b.y + c4.y + d4.y + bv.y, 0.f));
        __half2 r1 = __floats2half2_rn(
            fmaxf(a.z + b.z + c4.z + d4.z + bv.z, 0.f),
            fmaxf(a.w + b.w + c4.w + d4.w + bv.w, 0.f));
        ((__half2*)o)[2 * i]     = r0;
        ((__half2*)o)[2 * i + 1] = r1;
    }
}

// ---------------- GEMM2 2-way split-K reduce + bias + relu -> fp16 h2 ----------
__global__ __launch_bounds__(256) void reduce_relu2(
    const float* __restrict__ p, const float* __restrict__ bias, __half* __restrict__ o)
{
    const int tid = blockIdx.x * 256 + threadIdx.x;   // grid 128 -> 32768 threads
    const int S = BB * HID2 / 4;
    #pragma unroll
    for (int r = 0; r < 4; r++) {
        int i = tid + r * 32768;
        float4 a = ((const float4*)p)[i];
        float4 b = ((const float4*)p)[i + S];
        int c = (i * 4) & (HID2 - 1);
        float4 bv = *(const float4*)&bias[c];
        __half2 r0 = __floats2half2_rn(fmaxf(a.x + b.x + bv.x, 0.f), fmaxf(a.y + b.y + bv.y, 0.f));
        __half2 r1 = __floats2half2_rn(fmaxf(a.z + b.z + bv.z, 0.f), fmaxf(a.w + b.w + bv.w, 0.f));
        ((__half2*)o)[2 * i]     = r0;
        ((__half2*)o)[2 * i + 1] = r1;
    }
}

// ---------------- softmax over BATCH axis, fused 4-way logits reduce ----------
__global__ __launch_bounds__(512) void softmax_kernel(
    const float* __restrict__ lp, const float* __restrict__ b4, float* __restrict__ out)
{
    const int ncol = blockIdx.x;
    const int t = threadIdx.x;
    __shared__ float red[512];

    const float bv = b4[ncol];
    const int S = BB * NN;
    float lv[4];
    #pragma unroll
    for (int r = 0; r < 4; r++) {
        int idx = (t + r * 512) * NN + ncol;
        lv[r] = (lp[idx] + lp[S + idx]) + (lp[2 * S + idx] + lp[3 * S + idx]) + bv;
    }

    float mx = lv[0];
    #pragma unroll
    for (int r = 1; r < 4; r++) mx = fmaxf(mx, lv[r]);
    red[t] = mx; __syncthreads();
    for (int s = 256; s > 0; s >>= 1) { if (t < s) red[t] = fmaxf(red[t], red[t + s]); __syncthreads(); }
    mx = red[0]; __syncthreads();

    float sum = 0.f;
    #pragma unroll
    for (int r = 0; r < 4; r++) { lv[r] = __expf(lv[r] - mx); sum += lv[r]; }
    red[t] = sum; __syncthreads();
    for (int s = 256; s > 0; s >>= 1) { if (t < s) red[t] += red[t + s]; __syncthreads(); }
    float inv = 1.f / red[0];

    #pragma unroll
    for (int r = 0; r < 4; r++) out[(t + r * 512) * NN + ncol] = lv[r] * inv;
}

// ---------------- launch ----------------
extern "C" void kernel_launch(void* const* d_in, const int* in_sizes, int n_in,
                              void* d_out, int out_size)
{
    const float* x         = (const float*)d_in[0];
    const float* edge_attr = (const float*)d_in[1];
    const float* user_s    = (const float*)d_in[2];
    const float* W_msg     = (const float*)d_in[3];
    const float* b_msg     = (const float*)d_in[4];
    const float* W_edge    = (const float*)d_in[5];
    const float* b_edge    = (const float*)d_in[6];
    const float* W_self    = (const float*)d_in[7];
    const float* b_self    = (const float*)d_in[8];
    const float* W1        = (const float*)d_in[9];
    const float* b1        = (const float*)d_in[10];
    const float* W2        = (const float*)d_in[11];
    const float* b2        = (const float*)d_in[12];
    const float* W3        = (const float*)d_in[13];
    const float* b3        = (const float*)d_in[14];
    const float* W4        = (const float*)d_in[15];
    const float* b4        = (const float*)d_in[16];
    const int*   edge_index = (const int*)d_in[17];
    float* out = (float*)d_out;

    __half *states, *h1, *h2, *w2h, *w3h, *w4h;
    float *h1p, *h2p, *lp;
    cudaGetSymbolAddress((void**)&states, g_states);
    cudaGetSymbolAddress((void**)&h1p, g_h1p);
    cudaGetSymbolAddress((void**)&h1, g_h1);
    cudaGetSymbolAddress((void**)&h2p, g_h2p);
    cudaGetSymbolAddress((void**)&h2, g_h2);
    cudaGetSymbolAddress((void**)&lp, g_lp);
    cudaGetSymbolAddress((void**)&w2h, g_w2h);
    cudaGetSymbolAddress((void**)&w3h, g_w3h);
    cudaGetSymbolAddress((void**)&w4h, g_w4h);

    const int smemG1 = 3 * (128 * 80 + 32 * (2 * 128 + 16));   // 56832
    const int smem64 = 3 * (64 * 80 + 32 * (2 * 64 + 16));     // 29184

    cudaFuncSetAttribute((const void*)hgemm<128, 128, true, false, float>,
                         cudaFuncAttributeMaxDynamicSharedMemorySize, smemG1);
    cudaFuncSetAttribute((const void*)hgemm<64, 64, true, false, float>,
                         cudaFuncAttributeMaxDynamicSharedMemorySize, smem64);

    graph_kernel<<<BB, 256>>>(x, edge_attr, user_s, W_msg, b_msg, W_edge, b_edge,
                              W_self, b_self, W1, b1, edge_index, W2, W3, W4);

    // GEMM1: fp16, BM=128 x BN=128, split-K=4 (1056/1056/1056/992) -> fp32 partials
    hgemm<128, 128, true, false, float><<<dim3(HID / 128, BB / 128, 4), 256, smemG1>>>(
        states, w2h, b2, h1p, BB, HID, 1056, SDIM, SDIM);
    reduce_relu<<<256, 256>>>(h1p, b2, h1);

    // GEMM2: split-K=2 (256 each) -> fp32 partials -> reduce+bias+relu
    hgemm<64, 64, true, false, float><<<dim3(HID2 / 64, BB / 64, 2), 256, smem64>>>(
        h1, w3h, b3, h2p, BB, HID2, 256, HID, HID);
    reduce_relu2<<<128, 256>>>(h2p, b3, h2);

    // GEMM3: split-K=4 (64 each) -> 128 CTAs
    hgemm<64, 64, true, false, float><<<dim3(NN / 64, BB / 64, 4), 256, smem64>>>(
        h2, w4h, b4, lp, BB, NN, 64, HID2, HID2);

    softmax_kernel<<<NN, 512>>>(lp, b4, out);
}